// round 5
// baseline (speedup 1.0000x reference)
#include <cuda_runtime.h>
#include <cstddef>
#include <cstdint>

// Problem constants
#define BB   8
#define NN   4096
#define CC   768
#define HH   12
#define HD   64
#define NWIN 16
#define NW   256
#define TC   2304

#define QKVSZ (BB*NWIN*HH*NW*HD)

// Device-only scratch (never pass these from host code: GB300 ATS would
// silently read the zeroed host shadow).
__device__ float g_Q[QKVSZ];
__device__ float g_K[QKVSZ];
__device__ float g_V[QKVSZ];
__device__ float g_att[BB*NN*CC];

// ---------------------------------------------------------------------------
// tf32 helpers
// ---------------------------------------------------------------------------
__device__ __forceinline__ unsigned tf32_rna(float x) {
    unsigned r;
    asm("cvt.rna.tf32.f32 %0, %1;" : "=r"(r) : "f"(x));
    return r;
}

#define MMA_TF32(c, A0, A1, A2, A3, B0, B1)                                   \
    asm volatile(                                                             \
        "mma.sync.aligned.m16n8k8.row.col.f32.tf32.tf32.f32 "                 \
        "{%0,%1,%2,%3}, {%4,%5,%6,%7}, {%8,%9}, {%0,%1,%2,%3};"               \
        : "+f"((c)[0]), "+f"((c)[1]), "+f"((c)[2]), "+f"((c)[3])              \
        : "r"(A0), "r"(A1), "r"(A2), "r"(A3), "r"(B0), "r"(B1))

#define F2U(x) __float_as_uint(x)

// smem k-interleave within an 8-wide k-step: col(j) = (j&3)*2 + (j>>2)
// so fragment pairs (k, k+4) are adjacent -> one LDS.64 each.
#define SKS 20   // padded row stride (floats): conflict-free fragment loads

// ---------------------------------------------------------------------------
// Shared GEMM core (tf32 hi/lo split). Computes a 128x128 (M x N) tile of
// A(128 x 768) @ W^T, where per-chunk loads are supplied by the caller via
// lambda-like macros. Implemented twice (qkv / proj) to keep epilogues fused.
// Block: 256 threads = 8 warps, warp tile 64x32, BK=16.
// ---------------------------------------------------------------------------

// Convert 8 consecutive fp32 (one k-block) to hi/lo tf32 and store interleaved
__device__ __forceinline__ void store_conv8(float* hi, float* lo, int row,
                                            int c0, const float4& v0, const float4& v1)
{
    float v[8] = {v0.x, v0.y, v0.z, v0.w, v1.x, v1.y, v1.z, v1.w};
    #pragma unroll
    for (int j = 0; j < 8; j++) {
        unsigned hb = tf32_rna(v[j]);
        float hf = __uint_as_float(hb);
        unsigned lb = tf32_rna(v[j] - hf);
        int col = c0 + ((j & 3) * 2 + (j >> 2));
        hi[row * SKS + col] = __uint_as_float(hb);
        lo[row * SKS + col] = __uint_as_float(lb);
    }
}

// ---------------------------------------------------------------------------
// Kernel 1: fused window-permute + QKV GEMM (tf32 mma, hi/lo split)
// ---------------------------------------------------------------------------
__global__ __launch_bounds__(256)
void qkv_kernel(const float* __restrict__ x, const float* __restrict__ w)
{
    __shared__ float As_hi[128 * SKS];
    __shared__ float As_lo[128 * SKS];
    __shared__ float Bs_hi[128 * SKS];
    __shared__ float Bs_lo[128 * SKS];

    const int tid  = threadIdx.x;
    const int lane = tid & 31;
    const int wid  = tid >> 5;
    const int wm   = (wid >> 2) * 64;   // warp M base: 0 / 64
    const int wn   = (wid & 3) * 32;    // warp N base: 0/32/64/96
    const int gidr = lane >> 2;         // groupID (0..7)
    const int tig  = lane & 3;          // threadID_in_group

    const int bx = blockIdx.x;          // 0..17
    const int by = blockIdx.y;          // 0..255

    const int m0  = by * 128;
    const int b   = m0 >> 12;
    const int p0  = m0 & 4095;
    const int wdx = p0 >> 8;
    const int wr  = wdx >> 2, wc = wdx & 3;
    const int nin0 = p0 & 255;

    // Global load assignment: row = tid>>1, k-halfblock = (tid&1)*8
    const int rowL = tid >> 1;
    const int c0L  = (tid & 1) * 8;
    const int ninL = nin0 + rowL;
    const int norigL = wr*1024 + (ninL >> 4)*64 + wc*16 + (ninL & 15);
    const float* aptr = x + ((size_t)b*NN + norigL) * CC + c0L;
    const float* bptr = w + (size_t)(bx*128 + rowL) * CC + c0L;

    float acc[4][4][4];
    #pragma unroll
    for (int i = 0; i < 4; i++)
        #pragma unroll
        for (int j = 0; j < 4; j++)
            #pragma unroll
            for (int r = 0; r < 4; r++) acc[i][j][r] = 0.0f;

    // Prefetch chunk 0
    float4 ra0 = *(const float4*)(aptr + 0);
    float4 ra1 = *(const float4*)(aptr + 4);
    float4 rb0 = *(const float4*)(bptr + 0);
    float4 rb1 = *(const float4*)(bptr + 4);

    for (int kt = 0; kt < CC; kt += 16) {
        store_conv8(As_hi, As_lo, rowL, c0L, ra0, ra1);
        store_conv8(Bs_hi, Bs_lo, rowL, c0L, rb0, rb1);
        __syncthreads();

        if (kt + 16 < CC) {
            ra0 = *(const float4*)(aptr + kt + 16);
            ra1 = *(const float4*)(aptr + kt + 20);
            rb0 = *(const float4*)(bptr + kt + 16);
            rb1 = *(const float4*)(bptr + kt + 20);
        }

        #pragma unroll
        for (int ks = 0; ks < 2; ks++) {
            const int kc = ks * 8 + tig * 2;
            float2 ahi[4][2], alo[4][2], bhi[4], blo[4];
            #pragma unroll
            for (int mt = 0; mt < 4; mt++) {
                const int r0 = wm + mt*16 + gidr;
                ahi[mt][0] = *(const float2*)&As_hi[r0*SKS + kc];
                ahi[mt][1] = *(const float2*)&As_hi[(r0+8)*SKS + kc];
                alo[mt][0] = *(const float2*)&As_lo[r0*SKS + kc];
                alo[mt][1] = *(const float2*)&As_lo[(r0+8)*SKS + kc];
            }
            #pragma unroll
            for (int nt = 0; nt < 4; nt++) {
                const int n0 = wn + nt*8 + gidr;
                bhi[nt] = *(const float2*)&Bs_hi[n0*SKS + kc];
                blo[nt] = *(const float2*)&Bs_lo[n0*SKS + kc];
            }
            #pragma unroll
            for (int mt = 0; mt < 4; mt++) {
                #pragma unroll
                for (int nt = 0; nt < 4; nt++) {
                    // fragments: {a0,a1,a2,a3} = {lo.x of row, x of row+8, .y, .y}
                    MMA_TF32(acc[mt][nt],
                        F2U(ahi[mt][0].x), F2U(ahi[mt][1].x),
                        F2U(ahi[mt][0].y), F2U(ahi[mt][1].y),
                        F2U(bhi[nt].x),    F2U(bhi[nt].y));
                    MMA_TF32(acc[mt][nt],
                        F2U(alo[mt][0].x), F2U(alo[mt][1].x),
                        F2U(alo[mt][0].y), F2U(alo[mt][1].y),
                        F2U(bhi[nt].x),    F2U(bhi[nt].y));
                    MMA_TF32(acc[mt][nt],
                        F2U(ahi[mt][0].x), F2U(ahi[mt][1].x),
                        F2U(ahi[mt][0].y), F2U(ahi[mt][1].y),
                        F2U(blo[nt].x),    F2U(blo[nt].y));
                }
            }
        }
        __syncthreads();
    }

    // Epilogue: scatter into g_Q/g_K/g_V [b][win][head][n][d]
    // Block's 128 output cols lie entirely in ONE of Q/K/V (768 = 6*128).
    const int which = (bx * 128) / CC;
    float* basep = (which == 0) ? g_Q : ((which == 1) ? g_K : g_V);
    const size_t wbase = (((size_t)b*NWIN + wdx)*HH) * NW * HD;

    #pragma unroll
    for (int mt = 0; mt < 4; mt++) {
        #pragma unroll
        for (int nt = 0; nt < 4; nt++) {
            const int m = wm + mt*16 + gidr;
            const int j = bx*128 + wn + nt*8 + tig*2 - which*CC;  // 0..767
            const int h  = j >> 6;
            const int d0 = j & 63;
            const int nin = nin0 + m;
            float* dst = basep + wbase + ((size_t)h*NW + nin)*HD + d0;
            *(float2*)dst = make_float2(acc[mt][nt][0], acc[mt][nt][1]);
            *(float2*)(dst + 8*HD) = make_float2(acc[mt][nt][2], acc[mt][nt][3]);
        }
    }
}

// ---------------------------------------------------------------------------
// Kernel 2: per-(batch,window,head) attention (unchanged; fp32 FFMA)
// ---------------------------------------------------------------------------
#define CHUNK 64

__global__ __launch_bounds__(256, 1)
void attn_kernel()
{
    __shared__ float ks[CHUNK * HD];
    __shared__ float vs[CHUNK * HD];

    const int bid = blockIdx.x;
    const int h   = bid % HH;
    const int bw  = bid / HH;
    const int wdx = bw % NWIN;
    const int b   = bw / NWIN;

    const size_t base = ((((size_t)b*NWIN + wdx)*HH + h) * NW) * HD;
    const int tid = threadIdx.x;

    float q[64];
    {
        const float4* gq = (const float4*)(g_Q + base + (size_t)tid * HD);
        #pragma unroll
        for (int d4 = 0; d4 < 16; d4++) {
            float4 t = gq[d4];
            q[d4*4+0] = t.x; q[d4*4+1] = t.y; q[d4*4+2] = t.z; q[d4*4+3] = t.w;
        }
    }

    float o[64];
    #pragma unroll
    for (int d = 0; d < 64; d++) o[d] = 0.0f;
    float l = 0.0f;

    for (int c0 = 0; c0 < NW; c0 += CHUNK) {
        const float4* gk = (const float4*)(g_K + base + (size_t)c0 * HD);
        const float4* gv = (const float4*)(g_V + base + (size_t)c0 * HD);
        float4* k4 = (float4*)ks;
        float4* v4 = (float4*)vs;
        #pragma unroll
        for (int i = 0; i < (CHUNK*HD)/4/256; i++) {
            k4[tid + i*256] = gk[tid + i*256];
            v4[tid + i*256] = gv[tid + i*256];
        }
        __syncthreads();

        #pragma unroll 2
        for (int j = 0; j < CHUNK; j++) {
            const float4* kj = (const float4*)(ks + j*HD);
            float s = 0.0f;
            #pragma unroll
            for (int d4 = 0; d4 < 16; d4++) {
                float4 kv = kj[d4];
                s += q[d4*4+0]*kv.x + q[d4*4+1]*kv.y + q[d4*4+2]*kv.z + q[d4*4+3]*kv.w;
            }
            float e = __expf(s * 0.125f);
            l += e;
            const float4* vj = (const float4*)(vs + j*HD);
            #pragma unroll
            for (int d4 = 0; d4 < 16; d4++) {
                float4 vv = vj[d4];
                o[d4*4+0] += e*vv.x; o[d4*4+1] += e*vv.y;
                o[d4*4+2] += e*vv.z; o[d4*4+3] += e*vv.w;
            }
        }
        __syncthreads();
    }

    const float inv = 1.0f / l;
    const int nin = tid;
    const int r = nin >> 4, c = nin & 15;
    const int wr = wdx >> 2, wc = wdx & 3;
    const int norig = wr*1024 + r*64 + wc*16 + c;
    float4* dst = (float4*)(g_att + ((size_t)b*NN + norig) * CC + h * HD);
    #pragma unroll
    for (int d4 = 0; d4 < 16; d4++) {
        dst[d4] = make_float4(o[d4*4+0]*inv, o[d4*4+1]*inv,
                              o[d4*4+2]*inv, o[d4*4+3]*inv);
    }
}

// ---------------------------------------------------------------------------
// Kernel 3: projection out = g_att @ proj_w^T + proj_b (tf32 mma, hi/lo)
// ---------------------------------------------------------------------------
__global__ __launch_bounds__(256)
void proj_kernel(const float* __restrict__ w,
                 const float* __restrict__ bias, float* __restrict__ out)
{
    __shared__ float As_hi[128 * SKS];
    __shared__ float As_lo[128 * SKS];
    __shared__ float Bs_hi[128 * SKS];
    __shared__ float Bs_lo[128 * SKS];

    const float* a = g_att;

    const int tid  = threadIdx.x;
    const int lane = tid & 31;
    const int wid  = tid >> 5;
    const int wm   = (wid >> 2) * 64;
    const int wn   = (wid & 3) * 32;
    const int gidr = lane >> 2;
    const int tig  = lane & 3;

    const int bx = blockIdx.x;   // 0..5
    const int by = blockIdx.y;   // 0..255
    const int m0 = by * 128;

    const int rowL = tid >> 1;
    const int c0L  = (tid & 1) * 8;
    const float* aptr = a + (size_t)(m0 + rowL) * CC + c0L;
    const float* bptr = w + (size_t)(bx*128 + rowL) * CC + c0L;

    float acc[4][4][4];
    #pragma unroll
    for (int i = 0; i < 4; i++)
        #pragma unroll
        for (int j = 0; j < 4; j++)
            #pragma unroll
            for (int r = 0; r < 4; r++) acc[i][j][r] = 0.0f;

    float4 ra0 = *(const float4*)(aptr + 0);
    float4 ra1 = *(const float4*)(aptr + 4);
    float4 rb0 = *(const float4*)(bptr + 0);
    float4 rb1 = *(const float4*)(bptr + 4);

    for (int kt = 0; kt < CC; kt += 16) {
        store_conv8(As_hi, As_lo, rowL, c0L, ra0, ra1);
        store_conv8(Bs_hi, Bs_lo, rowL, c0L, rb0, rb1);
        __syncthreads();

        if (kt + 16 < CC) {
            ra0 = *(const float4*)(aptr + kt + 16);
            ra1 = *(const float4*)(aptr + kt + 20);
            rb0 = *(const float4*)(bptr + kt + 16);
            rb1 = *(const float4*)(bptr + kt + 20);
        }

        #pragma unroll
        for (int ks = 0; ks < 2; ks++) {
            const int kc = ks * 8 + tig * 2;
            float2 ahi[4][2], alo[4][2], bhi[4], blo[4];
            #pragma unroll
            for (int mt = 0; mt < 4; mt++) {
                const int r0 = wm + mt*16 + gidr;
                ahi[mt][0] = *(const float2*)&As_hi[r0*SKS + kc];
                ahi[mt][1] = *(const float2*)&As_hi[(r0+8)*SKS + kc];
                alo[mt][0] = *(const float2*)&As_lo[r0*SKS + kc];
                alo[mt][1] = *(const float2*)&As_lo[(r0+8)*SKS + kc];
            }
            #pragma unroll
            for (int nt = 0; nt < 4; nt++) {
                const int n0 = wn + nt*8 + gidr;
                bhi[nt] = *(const float2*)&Bs_hi[n0*SKS + kc];
                blo[nt] = *(const float2*)&Bs_lo[n0*SKS + kc];
            }
            #pragma unroll
            for (int mt = 0; mt < 4; mt++) {
                #pragma unroll
                for (int nt = 0; nt < 4; nt++) {
                    MMA_TF32(acc[mt][nt],
                        F2U(ahi[mt][0].x), F2U(ahi[mt][1].x),
                        F2U(ahi[mt][0].y), F2U(ahi[mt][1].y),
                        F2U(bhi[nt].x),    F2U(bhi[nt].y));
                    MMA_TF32(acc[mt][nt],
                        F2U(alo[mt][0].x), F2U(alo[mt][1].x),
                        F2U(alo[mt][0].y), F2U(alo[mt][1].y),
                        F2U(bhi[nt].x),    F2U(bhi[nt].y));
                    MMA_TF32(acc[mt][nt],
                        F2U(ahi[mt][0].x), F2U(ahi[mt][1].x),
                        F2U(ahi[mt][0].y), F2U(ahi[mt][1].y),
                        F2U(blo[nt].x),    F2U(blo[nt].y));
                }
            }
        }
        __syncthreads();
    }

    #pragma unroll
    for (int mt = 0; mt < 4; mt++) {
        #pragma unroll
        for (int nt = 0; nt < 4; nt++) {
            const int m = wm + mt*16 + gidr;
            const int j = bx*128 + wn + nt*8 + tig*2;
            const float b0 = bias[j], b1 = bias[j+1];
            float* d0 = out + (size_t)(m0 + m) * CC + j;
            *(float2*)d0 = make_float2(acc[mt][nt][0] + b0, acc[mt][nt][1] + b1);
            float* d1 = out + (size_t)(m0 + m + 8) * CC + j;
            *(float2*)d1 = make_float2(acc[mt][nt][2] + b0, acc[mt][nt][3] + b1);
        }
    }
}

// ---------------------------------------------------------------------------
extern "C" void kernel_launch(void* const* d_in, const int* in_sizes, int n_in,
                              void* d_out, int out_size)
{
    const float* x      = nullptr;
    const float* qkv_w  = nullptr;
    const float* proj_w = nullptr;
    const float* proj_b = nullptr;
    for (int i = 0; i < n_in; i++) {
        switch (in_sizes[i]) {
            case 25165824: x      = (const float*)d_in[i]; break;
            case 1769472:  qkv_w  = (const float*)d_in[i]; break;
            case 589824:   proj_w = (const float*)d_in[i]; break;
            case 768:      proj_b = (const float*)d_in[i]; break;
            default: break;
        }
    }
    if (!x || !qkv_w || !proj_w || !proj_b) {
        x      = (const float*)d_in[0];
        qkv_w  = (const float*)d_in[1];
        proj_w = (const float*)d_in[2];
        proj_b = (const float*)d_in[3];
    }
    float* out = (float*)d_out;
    (void)out_size;

    qkv_kernel<<<dim3(18, 256), 256>>>(x, qkv_w);
    attn_kernel<<<BB * NWIN * HH, 256>>>();
    proj_kernel<<<dim3(6, 256), 256>>>(proj_w, proj_b, out);
}

// round 8
// speedup vs baseline: 1.3999x; 1.3999x over previous
#include <cuda_runtime.h>
#include <cstddef>
#include <cstdint>

// Problem constants
#define BB   8
#define NN   4096
#define CC   768
#define HH   12
#define HD   64
#define NWIN 16
#define NW   256
#define TC   2304

#define QKVSZ (BB*NWIN*HH*NW*HD)

// Device-only scratch (never pass these from host code: GB300 ATS would
// silently read the zeroed host shadow).
__device__ float g_Q[QKVSZ];
__device__ float g_K[QKVSZ];
__device__ float g_V[QKVSZ];
__device__ float g_att[BB*NN*CC];

// ---------------------------------------------------------------------------
// tf32 helpers
// ---------------------------------------------------------------------------
__device__ __forceinline__ unsigned tf32_rna(float x) {
    unsigned r;
    asm("cvt.rna.tf32.f32 %0, %1;" : "=r"(r) : "f"(x));
    return r;
}

#define MMA_TF32(c, A0, A1, A2, A3, B0, B1)                                   \
    asm volatile(                                                             \
        "mma.sync.aligned.m16n8k8.row.col.f32.tf32.tf32.f32 "                 \
        "{%0,%1,%2,%3}, {%4,%5,%6,%7}, {%8,%9}, {%0,%1,%2,%3};"               \
        : "+f"((c)[0]), "+f"((c)[1]), "+f"((c)[2]), "+f"((c)[3])              \
        : "r"(A0), "r"(A1), "r"(A2), "r"(A3), "r"(B0), "r"(B1))

#define F2U(x) __float_as_uint(x)

// smem k-interleave within an 8-wide k-step: col(j) = (j&3)*2 + (j>>2)
#define SKS 20   // padded row stride (floats)

// A: hi/lo split (A is exact to fp32). B: hi only (error = B tf32 rounding,
// rms ~2.8e-4, well under the 1e-3 gate).
__device__ __forceinline__ void store_convA(float* hi, float* lo, int row,
                                            int c0, const float4& v0, const float4& v1)
{
    float v[8] = {v0.x, v0.y, v0.z, v0.w, v1.x, v1.y, v1.z, v1.w};
    #pragma unroll
    for (int j = 0; j < 8; j++) {
        unsigned hb = tf32_rna(v[j]);
        float hf = __uint_as_float(hb);
        unsigned lb = tf32_rna(v[j] - hf);
        int col = c0 + ((j & 3) * 2 + (j >> 2));
        hi[row * SKS + col] = __uint_as_float(hb);
        lo[row * SKS + col] = __uint_as_float(lb);
    }
}

__device__ __forceinline__ void store_convB(float* hi, int row,
                                            int c0, const float4& v0, const float4& v1)
{
    float v[8] = {v0.x, v0.y, v0.z, v0.w, v1.x, v1.y, v1.z, v1.w};
    #pragma unroll
    for (int j = 0; j < 8; j++) {
        int col = c0 + ((j & 3) * 2 + (j >> 2));
        hi[row * SKS + col] = __uint_as_float(tf32_rna(v[j]));
    }
}

// ---------------------------------------------------------------------------
// Kernel 1: fused window-permute + QKV GEMM (tf32 mma, A-split only)
// 128x128 tile, 8 warps (64x32 each), BK=16, 2 CTAs/SM.
// ---------------------------------------------------------------------------
__global__ __launch_bounds__(256, 2)
void qkv_kernel(const float* __restrict__ x, const float* __restrict__ w)
{
    __shared__ float As_hi[128 * SKS];
    __shared__ float As_lo[128 * SKS];
    __shared__ float Bs_hi[128 * SKS];

    const int tid  = threadIdx.x;
    const int lane = tid & 31;
    const int wid  = tid >> 5;
    const int wm   = (wid >> 2) * 64;
    const int wn   = (wid & 3) * 32;
    const int gidr = lane >> 2;
    const int tig  = lane & 3;

    const int bx = blockIdx.x;          // 0..17
    const int by = blockIdx.y;          // 0..255

    const int m0  = by * 128;
    const int b   = m0 >> 12;
    const int p0  = m0 & 4095;
    const int wdx = p0 >> 8;
    const int wr  = wdx >> 2, wc = wdx & 3;
    const int nin0 = p0 & 255;

    const int rowL = tid >> 1;
    const int c0L  = (tid & 1) * 8;
    const int ninL = nin0 + rowL;
    const int norigL = wr*1024 + (ninL >> 4)*64 + wc*16 + (ninL & 15);
    const float* aptr = x + ((size_t)b*NN + norigL) * CC + c0L;
    const float* bptr = w + (size_t)(bx*128 + rowL) * CC + c0L;

    float acc[4][4][4];
    #pragma unroll
    for (int i = 0; i < 4; i++)
        #pragma unroll
        for (int j = 0; j < 4; j++)
            #pragma unroll
            for (int r = 0; r < 4; r++) acc[i][j][r] = 0.0f;

    float4 ra0 = *(const float4*)(aptr + 0);
    float4 ra1 = *(const float4*)(aptr + 4);
    float4 rb0 = *(const float4*)(bptr + 0);
    float4 rb1 = *(const float4*)(bptr + 4);

    for (int kt = 0; kt < CC; kt += 16) {
        store_convA(As_hi, As_lo, rowL, c0L, ra0, ra1);
        store_convB(Bs_hi, rowL, c0L, rb0, rb1);
        __syncthreads();

        if (kt + 16 < CC) {
            ra0 = *(const float4*)(aptr + kt + 16);
            ra1 = *(const float4*)(aptr + kt + 20);
            rb0 = *(const float4*)(bptr + kt + 16);
            rb1 = *(const float4*)(bptr + kt + 20);
        }

        #pragma unroll
        for (int ks = 0; ks < 2; ks++) {
            const int kc = ks * 8 + tig * 2;
            float2 ahi[4][2], alo[4][2], bhi[4];
            #pragma unroll
            for (int mt = 0; mt < 4; mt++) {
                const int r0 = wm + mt*16 + gidr;
                ahi[mt][0] = *(const float2*)&As_hi[r0*SKS + kc];
                ahi[mt][1] = *(const float2*)&As_hi[(r0+8)*SKS + kc];
                alo[mt][0] = *(const float2*)&As_lo[r0*SKS + kc];
                alo[mt][1] = *(const float2*)&As_lo[(r0+8)*SKS + kc];
            }
            #pragma unroll
            for (int nt = 0; nt < 4; nt++) {
                const int n0 = wn + nt*8 + gidr;
                bhi[nt] = *(const float2*)&Bs_hi[n0*SKS + kc];
            }
            #pragma unroll
            for (int mt = 0; mt < 4; mt++) {
                #pragma unroll
                for (int nt = 0; nt < 4; nt++) {
                    MMA_TF32(acc[mt][nt],
                        F2U(ahi[mt][0].x), F2U(ahi[mt][1].x),
                        F2U(ahi[mt][0].y), F2U(ahi[mt][1].y),
                        F2U(bhi[nt].x),    F2U(bhi[nt].y));
                    MMA_TF32(acc[mt][nt],
                        F2U(alo[mt][0].x), F2U(alo[mt][1].x),
                        F2U(alo[mt][0].y), F2U(alo[mt][1].y),
                        F2U(bhi[nt].x),    F2U(bhi[nt].y));
                }
            }
        }
        __syncthreads();
    }

    // Scatter into g_Q/g_K/g_V [b][win][head][n][d]
    const int which = (bx * 128) / CC;
    float* basep = (which == 0) ? g_Q : ((which == 1) ? g_K : g_V);
    const size_t wbase = (((size_t)b*NWIN + wdx)*HH) * NW * HD;

    #pragma unroll
    for (int mt = 0; mt < 4; mt++) {
        #pragma unroll
        for (int nt = 0; nt < 4; nt++) {
            const int m = wm + mt*16 + gidr;
            const int j = bx*128 + wn + nt*8 + tig*2 - which*CC;
            const int h  = j >> 6;
            const int d0 = j & 63;
            const int nin = nin0 + m;
            float* dst = basep + wbase + ((size_t)h*NW + nin)*HD + d0;
            *(float2*)dst = make_float2(acc[mt][nt][0], acc[mt][nt][1]);
            *(float2*)(dst + 8*HD) = make_float2(acc[mt][nt][2], acc[mt][nt][3]);
        }
    }
}

// ---------------------------------------------------------------------------
// Kernel 2: per-(batch,window,head) attention (fp32 FFMA, unchanged)
// ---------------------------------------------------------------------------
#define CHUNK 64

__global__ __launch_bounds__(256, 1)
void attn_kernel()
{
    __shared__ float ks[CHUNK * HD];
    __shared__ float vs[CHUNK * HD];

    const int bid = blockIdx.x;
    const int h   = bid % HH;
    const int bw  = bid / HH;
    const int wdx = bw % NWIN;
    const int b   = bw / NWIN;

    const size_t base = ((((size_t)b*NWIN + wdx)*HH + h) * NW) * HD;
    const int tid = threadIdx.x;

    float q[64];
    {
        const float4* gq = (const float4*)(g_Q + base + (size_t)tid * HD);
        #pragma unroll
        for (int d4 = 0; d4 < 16; d4++) {
            float4 t = gq[d4];
            q[d4*4+0] = t.x; q[d4*4+1] = t.y; q[d4*4+2] = t.z; q[d4*4+3] = t.w;
        }
    }

    float o[64];
    #pragma unroll
    for (int d = 0; d < 64; d++) o[d] = 0.0f;
    float l = 0.0f;

    for (int c0 = 0; c0 < NW; c0 += CHUNK) {
        const float4* gk = (const float4*)(g_K + base + (size_t)c0 * HD);
        const float4* gv = (const float4*)(g_V + base + (size_t)c0 * HD);
        float4* k4 = (float4*)ks;
        float4* v4 = (float4*)vs;
        #pragma unroll
        for (int i = 0; i < (CHUNK*HD)/4/256; i++) {
            k4[tid + i*256] = gk[tid + i*256];
            v4[tid + i*256] = gv[tid + i*256];
        }
        __syncthreads();

        #pragma unroll 2
        for (int j = 0; j < CHUNK; j++) {
            const float4* kj = (const float4*)(ks + j*HD);
            float s = 0.0f;
            #pragma unroll
            for (int d4 = 0; d4 < 16; d4++) {
                float4 kv = kj[d4];
                s += q[d4*4+0]*kv.x + q[d4*4+1]*kv.y + q[d4*4+2]*kv.z + q[d4*4+3]*kv.w;
            }
            float e = __expf(s * 0.125f);
            l += e;
            const float4* vj = (const float4*)(vs + j*HD);
            #pragma unroll
            for (int d4 = 0; d4 < 16; d4++) {
                float4 vv = vj[d4];
                o[d4*4+0] += e*vv.x; o[d4*4+1] += e*vv.y;
                o[d4*4+2] += e*vv.z; o[d4*4+3] += e*vv.w;
            }
        }
        __syncthreads();
    }

    const float inv = 1.0f / l;
    const int nin = tid;
    const int r = nin >> 4, c = nin & 15;
    const int wr = wdx >> 2, wc = wdx & 3;
    const int norig = wr*1024 + r*64 + wc*16 + c;
    float4* dst = (float4*)(g_att + ((size_t)b*NN + norig) * CC + h * HD);
    #pragma unroll
    for (int d4 = 0; d4 < 16; d4++) {
        dst[d4] = make_float4(o[d4*4+0]*inv, o[d4*4+1]*inv,
                              o[d4*4+2]*inv, o[d4*4+3]*inv);
    }
}

// ---------------------------------------------------------------------------
// Kernel 3: projection out = g_att @ proj_w^T + proj_b (tf32, A-split only)
// ---------------------------------------------------------------------------
__global__ __launch_bounds__(256, 2)
void proj_kernel(const float* __restrict__ w,
                 const float* __restrict__ bias, float* __restrict__ out)
{
    __shared__ float As_hi[128 * SKS];
    __shared__ float As_lo[128 * SKS];
    __shared__ float Bs_hi[128 * SKS];

    const float* a = g_att;

    const int tid  = threadIdx.x;
    const int lane = tid & 31;
    const int wid  = tid >> 5;
    const int wm   = (wid >> 2) * 64;
    const int wn   = (wid & 3) * 32;
    const int gidr = lane >> 2;
    const int tig  = lane & 3;

    const int bx = blockIdx.x;   // 0..5
    const int by = blockIdx.y;   // 0..255
    const int m0 = by * 128;

    const int rowL = tid >> 1;
    const int c0L  = (tid & 1) * 8;
    const float* aptr = a + (size_t)(m0 + rowL) * CC + c0L;
    const float* bptr = w + (size_t)(bx*128 + rowL) * CC + c0L;

    float acc[4][4][4];
    #pragma unroll
    for (int i = 0; i < 4; i++)
        #pragma unroll
        for (int j = 0; j < 4; j++)
            #pragma unroll
            for (int r = 0; r < 4; r++) acc[i][j][r] = 0.0f;

    float4 ra0 = *(const float4*)(aptr + 0);
    float4 ra1 = *(const float4*)(aptr + 4);
    float4 rb0 = *(const float4*)(bptr + 0);
    float4 rb1 = *(const float4*)(bptr + 4);

    for (int kt = 0; kt < CC; kt += 16) {
        store_convA(As_hi, As_lo, rowL, c0L, ra0, ra1);
        store_convB(Bs_hi, rowL, c0L, rb0, rb1);
        __syncthreads();

        if (kt + 16 < CC) {
            ra0 = *(const float4*)(aptr + kt + 16);
            ra1 = *(const float4*)(aptr + kt + 20);
            rb0 = *(const float4*)(bptr + kt + 16);
            rb1 = *(const float4*)(bptr + kt + 20);
        }

        #pragma unroll
        for (int ks = 0; ks < 2; ks++) {
            const int kc = ks * 8 + tig * 2;
            float2 ahi[4][2], alo[4][2], bhi[4];
            #pragma unroll
            for (int mt = 0; mt < 4; mt++) {
                const int r0 = wm + mt*16 + gidr;
                ahi[mt][0] = *(const float2*)&As_hi[r0*SKS + kc];
                ahi[mt][1] = *(const float2*)&As_hi[(r0+8)*SKS + kc];
                alo[mt][0] = *(const float2*)&As_lo[r0*SKS + kc];
                alo[mt][1] = *(const float2*)&As_lo[(r0+8)*SKS + kc];
            }
            #pragma unroll
            for (int nt = 0; nt < 4; nt++) {
                const int n0 = wn + nt*8 + gidr;
                bhi[nt] = *(const float2*)&Bs_hi[n0*SKS + kc];
            }
            #pragma unroll
            for (int mt = 0; mt < 4; mt++) {
                #pragma unroll
                for (int nt = 0; nt < 4; nt++) {
                    MMA_TF32(acc[mt][nt],
                        F2U(ahi[mt][0].x), F2U(ahi[mt][1].x),
                        F2U(ahi[mt][0].y), F2U(ahi[mt][1].y),
                        F2U(bhi[nt].x),    F2U(bhi[nt].y));
                    MMA_TF32(acc[mt][nt],
                        F2U(alo[mt][0].x), F2U(alo[mt][1].x),
                        F2U(alo[mt][0].y), F2U(alo[mt][1].y),
                        F2U(bhi[nt].x),    F2U(bhi[nt].y));
                }
            }
        }
        __syncthreads();
    }

    #pragma unroll
    for (int mt = 0; mt < 4; mt++) {
        #pragma unroll
        for (int nt = 0; nt < 4; nt++) {
            const int m = wm + mt*16 + gidr;
            const int j = bx*128 + wn + nt*8 + tig*2;
            const float b0 = bias[j], b1 = bias[j+1];
            float* d0 = out + (size_t)(m0 + m) * CC + j;
            *(float2*)d0 = make_float2(acc[mt][nt][0] + b0, acc[mt][nt][1] + b1);
            float* d1 = out + (size_t)(m0 + m + 8) * CC + j;
            *(float2*)d1 = make_float2(acc[mt][nt][2] + b0, acc[mt][nt][3] + b1);
        }
    }
}

// ---------------------------------------------------------------------------
extern "C" void kernel_launch(void* const* d_in, const int* in_sizes, int n_in,
                              void* d_out, int out_size)
{
    const float* x      = nullptr;
    const float* qkv_w  = nullptr;
    const float* proj_w = nullptr;
    const float* proj_b = nullptr;
    for (int i = 0; i < n_in; i++) {
        switch (in_sizes[i]) {
            case 25165824: x      = (const float*)d_in[i]; break;
            case 1769472:  qkv_w  = (const float*)d_in[i]; break;
            case 589824:   proj_w = (const float*)d_in[i]; break;
            case 768:      proj_b = (const float*)d_in[i]; break;
            default: break;
        }
    }
    if (!x || !qkv_w || !proj_w || !proj_b) {
        x      = (const float*)d_in[0];
        qkv_w  = (const float*)d_in[1];
        proj_w = (const float*)d_in[2];
        proj_b = (const float*)d_in[3];
    }
    float* out = (float*)d_out;
    (void)out_size;

    qkv_kernel<<<dim3(18, 256), 256>>>(x, qkv_w);
    attn_kernel<<<BB * NWIN * HH, 256>>>();
    proj_kernel<<<dim3(6, 256), 256>>>(proj_w, proj_b, out);
}